// round 12
// baseline (speedup 1.0000x reference)
#include <cuda_runtime.h>
#include <cuda_bf16.h>
#include <cstdint>
#include <math.h>

#define P_   1024
#define L_   32
#define E_   512
#define D_   768
#define NL_  6
#define FF_  3072
#define HPA_ 4
#define HTR_ 8

// ---------------- scratch (device globals; no allocation allowed) ----------------
__device__ float g_emb[P_ * L_ * E_];
__device__ float g_qkv[P_ * L_ * 3 * E_];
__device__ float g_ctx[P_ * L_ * E_];
__device__ float g_pr [P_ * E_];
__device__ float g_h  [P_ * D_];
__device__ float g_hn [P_ * D_];
__device__ float g_ff [P_ * FF_];
// bf16 hi/lo split buffers (max A = 32768x512, max W = 3072x768)
__device__ __nv_bfloat16 g_ahi[P_ * L_ * E_];
__device__ __nv_bfloat16 g_alo[P_ * L_ * E_];
__device__ __nv_bfloat16 g_whi[FF_ * D_];
__device__ __nv_bfloat16 g_wlo[FF_ * D_];

// ---------------- helpers ----------------
__device__ __forceinline__ float gelu_exact(float x) {
    return 0.5f * x * (1.0f + erff(x * 0.70710678118654752440f));
}
__device__ __forceinline__ uint32_t smem_u32(const void* p) {
    uint32_t a;
    asm("{ .reg .u64 t; cvta.to.shared.u64 t, %1; cvt.u32.u64 %0, t; }" : "=r"(a) : "l"(p));
    return a;
}
__device__ __forceinline__ void cp16(uint32_t dst, const void* src) {
    asm volatile("cp.async.cg.shared.global [%0], [%1], 16;" :: "r"(dst), "l"(src));
}
__device__ __forceinline__ void cp_commit() {
    asm volatile("cp.async.commit_group;" ::: "memory");
}
__device__ __forceinline__ void ldsm4(uint32_t& r0, uint32_t& r1, uint32_t& r2, uint32_t& r3,
                                      uint32_t addr) {
    asm volatile("ldmatrix.sync.aligned.m8n8.x4.shared.b16 {%0,%1,%2,%3}, [%4];"
                 : "=r"(r0), "=r"(r1), "=r"(r2), "=r"(r3) : "r"(addr));
}
__device__ __forceinline__ void mma_bf16(float* c, const uint32_t* a, const uint32_t* b) {
    asm volatile(
        "mma.sync.aligned.m16n8k16.row.col.f32.bf16.bf16.f32 "
        "{%0,%1,%2,%3}, {%4,%5,%6,%7}, {%8,%9}, {%0,%1,%2,%3};"
        : "+f"(c[0]), "+f"(c[1]), "+f"(c[2]), "+f"(c[3])
        : "r"(a[0]), "r"(a[1]), "r"(a[2]), "r"(a[3]), "r"(b[0]), "r"(b[1]));
}

// ---------------- fp32 -> bf16 hi/lo split ----------------
__global__ void split_kernel(const float* __restrict__ x, __nv_bfloat16* __restrict__ hi,
                             __nv_bfloat16* __restrict__ lo, int n4) {
    int i = blockIdx.x * 256 + threadIdx.x;
    if (i >= n4) return;
    float4 v = reinterpret_cast<const float4*>(x)[i];
    __nv_bfloat16 h0 = __float2bfloat16(v.x), h1 = __float2bfloat16(v.y);
    __nv_bfloat16 h2 = __float2bfloat16(v.z), h3 = __float2bfloat16(v.w);
    __nv_bfloat162* hp = reinterpret_cast<__nv_bfloat162*>(hi);
    __nv_bfloat162* lp = reinterpret_cast<__nv_bfloat162*>(lo);
    hp[2 * i]     = __nv_bfloat162(h0, h1);
    hp[2 * i + 1] = __nv_bfloat162(h2, h3);
    lp[2 * i]     = __nv_bfloat162(__float2bfloat16(v.x - __bfloat162float(h0)),
                                   __float2bfloat16(v.y - __bfloat162float(h1)));
    lp[2 * i + 1] = __nv_bfloat162(__float2bfloat16(v.z - __bfloat162float(h2)),
                                   __float2bfloat16(v.w - __bfloat162float(h3)));
}

// ---------------- HMMA GEMM: C[M,N] = epi(A@W^T + bias) (+Res) ----------------
// bf16 hi/lo operands, fp32 accum. BM=BN=128, BK=32, 512 threads (4x4 warps,
// 32x32 per warp). smem/stage: 4 tiles (Ahi,Alo,Bhi,Blo), 128 rows x 40 bf16.
#define TPAD    40
#define TILE_B  (128 * TPAD * 2)     // 10240
#define STAGE_B (4 * TILE_B)         // 40960
#define GSMEM   (2 * STAGE_B)        // 81920

template<int ACT>
__global__ void __launch_bounds__(512, 1)
mma_gemm(const __nv_bfloat16* __restrict__ Ahi, const __nv_bfloat16* __restrict__ Alo,
         const __nv_bfloat16* __restrict__ Whi, const __nv_bfloat16* __restrict__ Wlo,
         const float* __restrict__ bias, const float* __restrict__ Res,
         float* __restrict__ C, int M, int N, int K) {
    extern __shared__ char smem[];
    uint32_t sb = smem_u32(smem);
    int tid = threadIdx.x, lane = tid & 31, warp = tid >> 5;
    int wm = warp >> 2, wn = warp & 3;              // 4 x 4 warp grid, 32x32 each
    int m0 = blockIdx.y * 128, n0 = blockIdx.x * 128;

    float acc[2][4][4];
    #pragma unroll
    for (int mf = 0; mf < 2; mf++)
        #pragma unroll
        for (int nf = 0; nf < 4; nf++)
            #pragma unroll
            for (int q = 0; q < 4; q++) acc[mf][nf][q] = 0.0f;

    auto load_stage = [&](int s, int k0) {
        uint32_t base = sb + s * STAGE_B;
        int r = tid >> 2, c = tid & 3;              // 512 threads = 512 chunks/tile
        uint32_t doff = (uint32_t)(r * 80 + c * 16);
        size_t aoff = (size_t)(m0 + r) * K + k0 + c * 8;
        size_t boff = (size_t)(n0 + r) * K + k0 + c * 8;
        cp16(base + doff,              Ahi + aoff);
        cp16(base + TILE_B + doff,     Alo + aoff);
        cp16(base + 2 * TILE_B + doff, Whi + boff);
        cp16(base + 3 * TILE_B + doff, Wlo + boff);
        cp_commit();
    };

    auto compute_stage = [&](int s) {
        uint32_t base = sb + s * STAGE_B;
        #pragma unroll
        for (int ks = 0; ks < 2; ks++) {
            int kk = ks * 16;
            uint32_t ahi[2][4], alo[2][4];
            #pragma unroll
            for (int mf = 0; mf < 2; mf++) {
                int row = wm * 32 + mf * 16 + (lane & 15);
                int kc  = kk + ((lane >> 4) << 3);
                uint32_t off = (uint32_t)(row * 80 + kc * 2);
                ldsm4(ahi[mf][0], ahi[mf][1], ahi[mf][2], ahi[mf][3], base + off);
                ldsm4(alo[mf][0], alo[mf][1], alo[mf][2], alo[mf][3], base + TILE_B + off);
            }
            uint32_t bhi[4][2], blo[4][2];
            #pragma unroll
            for (int nq = 0; nq < 2; nq++) {
                int row = wn * 32 + nq * 16 + ((lane >> 4) << 3) + (lane & 7);
                int kc  = kk + (((lane >> 3) & 1) << 3);
                uint32_t off = (uint32_t)(row * 80 + kc * 2);
                uint32_t r0, r1, r2, r3;
                ldsm4(r0, r1, r2, r3, base + 2 * TILE_B + off);
                bhi[2 * nq][0] = r0; bhi[2 * nq][1] = r1;
                bhi[2 * nq + 1][0] = r2; bhi[2 * nq + 1][1] = r3;
                ldsm4(r0, r1, r2, r3, base + 3 * TILE_B + off);
                blo[2 * nq][0] = r0; blo[2 * nq][1] = r1;
                blo[2 * nq + 1][0] = r2; blo[2 * nq + 1][1] = r3;
            }
            #pragma unroll
            for (int mf = 0; mf < 2; mf++)
                #pragma unroll
                for (int nf = 0; nf < 4; nf++) {
                    mma_bf16(acc[mf][nf], ahi[mf], bhi[nf]);
                    mma_bf16(acc[mf][nf], ahi[mf], blo[nf]);
                    mma_bf16(acc[mf][nf], alo[mf], bhi[nf]);
                }
        }
    };

    int nk = K >> 5;
    load_stage(0, 0);
    for (int kt = 0; kt < nk; kt++) {
        if (kt + 1 < nk) {
            load_stage((kt + 1) & 1, (kt + 1) << 5);
            asm volatile("cp.async.wait_group 1;" ::: "memory");
        } else {
            asm volatile("cp.async.wait_group 0;" ::: "memory");
        }
        __syncthreads();
        compute_stage(kt & 1);
        __syncthreads();
    }

    // epilogue: fragment (mf,nf): rows m0+wm*32+mf*16+{lane/4, +8}, cols n0+wn*32+nf*8+(lane%4)*2
    #pragma unroll
    for (int mf = 0; mf < 2; mf++) {
        int rbase = m0 + wm * 32 + mf * 16 + (lane >> 2);
        #pragma unroll
        for (int nf = 0; nf < 4; nf++) {
            int cbase = n0 + wn * 32 + nf * 8 + (lane & 3) * 2;
            #pragma unroll
            for (int half = 0; half < 2; half++) {
                int m = rbase + half * 8;
                float2 v;
                v.x = acc[mf][nf][half * 2];
                v.y = acc[mf][nf][half * 2 + 1];
                if (bias) { v.x += bias[cbase]; v.y += bias[cbase + 1]; }
                if (ACT == 1) { v.x = gelu_exact(v.x); v.y = gelu_exact(v.y); }
                if (Res) {
                    const float2 rv = *reinterpret_cast<const float2*>(Res + (size_t)m * N + cbase);
                    v.x += rv.x; v.y += rv.y;
                }
                *reinterpret_cast<float2*>(C + (size_t)m * N + cbase) = v;
            }
        }
    }
}

// ---------------- embedding + mask ----------------
__global__ void embed_kernel(const int* __restrict__ tokens, const int* __restrict__ lengths,
                             const float* __restrict__ byte_emb, const float* __restrict__ lpos,
                             float* __restrict__ out) {
    int pl = blockIdx.x;
    int p  = pl >> 5;
    int l  = pl & 31;
    int t  = threadIdx.x;
    bool valid = (l < lengths[p]);
    int tok = tokens[pl];
    const float* be = byte_emb + (size_t)tok * E_;
    const float* lp = lpos + (size_t)l * E_;
    float* o = out + (size_t)pl * E_;
    #pragma unroll
    for (int e = t; e < E_; e += 256)
        o[e] = valid ? (be[e] + lp[e]) : 0.0f;
}

// ---------------- local (per-patch) attention: S=32, d=128, 4 heads ----------------
__global__ void __launch_bounds__(128)
local_attn_kernel(const float* __restrict__ qkv, const int* __restrict__ lengths,
                  float* __restrict__ ctx) {
    __shared__ float bufA[32][129];
    __shared__ float bufK[32][129];
    __shared__ float s[32][33];

    int p = blockIdx.x, h = blockIdx.y, t = threadIdx.x;
    int len = lengths[p];
    const float scale = 0.08838834764831845f;
    const float* base = qkv + (size_t)p * 32 * 1536 + h * 128;

    #pragma unroll 4
    for (int l = 0; l < 32; l++) {
        bufA[l][t] = base[(size_t)l * 1536 + t] * scale;
        bufK[l][t] = base[(size_t)l * 1536 + 512 + t];
    }
    __syncthreads();

    #pragma unroll
    for (int w = 0; w < 8; w++) {
        int idx = t + w * 128;
        int i = idx >> 5, j = idx & 31;
        float acc = 0.0f;
        #pragma unroll 8
        for (int kk = 0; kk < 128; kk++) acc = fmaf(bufA[i][kk], bufK[j][kk], acc);
        s[i][j] = (j < len) ? acc : -1e30f;
    }
    __syncthreads();

    if (t < 32) {
        float mx = -1e30f;
        #pragma unroll
        for (int j = 0; j < 32; j++) mx = fmaxf(mx, s[t][j]);
        float sum = 0.0f;
        #pragma unroll
        for (int j = 0; j < 32; j++) { float e = __expf(s[t][j] - mx); s[t][j] = e; sum += e; }
        float inv = 1.0f / sum;
        #pragma unroll
        for (int j = 0; j < 32; j++) s[t][j] *= inv;
    }
    __syncthreads();

    #pragma unroll 4
    for (int l = 0; l < 32; l++)
        bufA[l][t] = base[(size_t)l * 1536 + 1024 + t];
    __syncthreads();

    for (int l = 0; l < 32; l++) {
        float acc = 0.0f;
        #pragma unroll
        for (int j = 0; j < 32; j++) acc = fmaf(s[l][j], bufA[j][t], acc);
        ctx[(size_t)(p * 32 + l) * 512 + h * 128 + t] = acc;
    }
}

// ---------------- masked mean ----------------
__global__ void meanpool_kernel(const float* __restrict__ attn_out, const int* __restrict__ lengths,
                                float* __restrict__ pr) {
    int p = blockIdx.x, t = threadIdx.x;
    int len = lengths[p];
    const float* b = attn_out + (size_t)p * 32 * 512 + t;
    float acc = 0.0f;
    for (int l = 0; l < len; l++) acc += b[(size_t)l * 512];
    pr[(size_t)p * 512 + t] = acc / (float)len;
}

// ---------------- layernorm over D=768 ----------------
__global__ void ln_kernel(const float* __restrict__ x, const float* __restrict__ w,
                          const float* __restrict__ b, float* __restrict__ y) {
    __shared__ float red[8];
    int m = blockIdx.x, t = threadIdx.x;
    const float* xr = x + (size_t)m * D_;
    float v0 = xr[t], v1 = xr[t + 256], v2 = xr[t + 512];

    float s = v0 + v1 + v2;
    #pragma unroll
    for (int o = 16; o; o >>= 1) s += __shfl_xor_sync(0xffffffffu, s, o);
    if ((t & 31) == 0) red[t >> 5] = s;
    __syncthreads();
    if (t < 8) {
        float v = red[t];
        #pragma unroll
        for (int o = 4; o; o >>= 1) v += __shfl_xor_sync(0xffu, v, o);
        if (t == 0) red[0] = v;
    }
    __syncthreads();
    float mu = red[0] * (1.0f / D_);
    __syncthreads();

    float d0 = v0 - mu, d1 = v1 - mu, d2 = v2 - mu;
    float sq = d0 * d0 + d1 * d1 + d2 * d2;
    #pragma unroll
    for (int o = 16; o; o >>= 1) sq += __shfl_xor_sync(0xffffffffu, sq, o);
    if ((t & 31) == 0) red[t >> 5] = sq;
    __syncthreads();
    if (t < 8) {
        float v = red[t];
        #pragma unroll
        for (int o = 4; o; o >>= 1) v += __shfl_xor_sync(0xffu, v, o);
        if (t == 0) red[0] = v;
    }
    __syncthreads();
    float rstd = rsqrtf(red[0] * (1.0f / D_) + 1e-5f);

    float* yr = y + (size_t)m * D_;
    yr[t]       = d0 * rstd * w[t]       + b[t];
    yr[t + 256] = d1 * rstd * w[t + 256] + b[t + 256];
    yr[t + 512] = d2 * rstd * w[t + 512] + b[t + 512];
}

// ---------------- transformer attention: S=1024, d=96, 8 heads ----------------
__global__ void __launch_bounds__(128)
trans_attn_kernel(const float* __restrict__ qkv, float* __restrict__ ctx) {
    __shared__ float sQ[8][96];
    __shared__ float sKV[32][97];
    __shared__ float sS[8][1024];

    int qt = blockIdx.x, h = blockIdx.y, t = threadIdx.x;
    int q0 = qt * 8;
    const float scale = 0.10206207261596575f;

    for (int u = t; u < 8 * 96; u += 128) {
        int i = u / 96, dd = u - i * 96;
        sQ[i][dd] = qkv[(size_t)(q0 + i) * 2304 + h * 96 + dd] * scale;
    }
    __syncthreads();

    for (int kt = 0; kt < 32; kt++) {
        int j0 = kt * 32;
        for (int u = t; u < 32 * 96; u += 128) {
            int j = u / 96, dd = u - j * 96;
            sKV[j][dd] = qkv[(size_t)(j0 + j) * 2304 + 768 + h * 96 + dd];
        }
        __syncthreads();
        #pragma unroll
        for (int w = 0; w < 2; w++) {
            int idx = t + w * 128;
            int i = idx >> 5, j = idx & 31;
            float acc = 0.0f;
            #pragma unroll 8
            for (int kk = 0; kk < 96; kk++) acc = fmaf(sQ[i][kk], sKV[j][kk], acc);
            sS[i][j0 + j] = acc;
        }
        __syncthreads();
    }

    {
        int i = t >> 4, lane = t & 15;
        float mx = -1e30f;
        for (int j = lane; j < 1024; j += 16) mx = fmaxf(mx, sS[i][j]);
        #pragma unroll
        for (int o = 8; o; o >>= 1) mx = fmaxf(mx, __shfl_xor_sync(0xffffffffu, mx, o, 16));
        float sum = 0.0f;
        for (int j = lane; j < 1024; j += 16) { float e = __expf(sS[i][j] - mx); sS[i][j] = e; sum += e; }
        #pragma unroll
        for (int o = 8; o; o >>= 1) sum += __shfl_xor_sync(0xffffffffu, sum, o, 16);
        float inv = 1.0f / sum;
        for (int j = lane; j < 1024; j += 16) sS[i][j] *= inv;
    }
    __syncthreads();

    float acc[6] = {0, 0, 0, 0, 0, 0};
    int io[6], ddo[6];
    #pragma unroll
    for (int w = 0; w < 6; w++) { int o = t + w * 128; io[w] = o / 96; ddo[w] = o - io[w] * 96; }

    for (int vt = 0; vt < 32; vt++) {
        int j0 = vt * 32;
        for (int u = t; u < 32 * 96; u += 128) {
            int j = u / 96, dd = u - j * 96;
            sKV[j][dd] = qkv[(size_t)(j0 + j) * 2304 + 1536 + h * 96 + dd];
        }
        __syncthreads();
        #pragma unroll
        for (int w = 0; w < 6; w++) {
            float a = 0.0f;
            #pragma unroll
            for (int j = 0; j < 32; j++) a = fmaf(sS[io[w]][j0 + j], sKV[j][ddo[w]], a);
            acc[w] += a;
        }
        __syncthreads();
    }
    #pragma unroll
    for (int w = 0; w < 6; w++)
        ctx[(size_t)(q0 + io[w]) * 768 + h * 96 + ddo[w]] = acc[w];
}

// ---------------- host driver ----------------
static void run_gemm(const float* A, const float* W, const float* bias, const float* Res,
                     float* C, int M, int N, int K, int act,
                     __nv_bfloat16* ahi, __nv_bfloat16* alo,
                     __nv_bfloat16* whi, __nv_bfloat16* wlo) {
    int na4 = (M * K) / 4, nw4 = (N * K) / 4;
    split_kernel<<<(na4 + 255) / 256, 256>>>(A, ahi, alo, na4);
    split_kernel<<<(nw4 + 255) / 256, 256>>>(W, whi, wlo, nw4);
    dim3 grid(N / 128, M / 128), block(512);
    if (act) mma_gemm<1><<<grid, block, GSMEM>>>(ahi, alo, whi, wlo, bias, Res, C, M, N, K);
    else     mma_gemm<0><<<grid, block, GSMEM>>>(ahi, alo, whi, wlo, bias, Res, C, M, N, K);
}

extern "C" void kernel_launch(void* const* d_in, const int* in_sizes, int n_in,
                              void* d_out, int out_size) {
    const int*   tokens   = (const int*)d_in[0];
    const int*   lengths  = (const int*)d_in[1];
    const float* byte_emb = (const float*)d_in[2];
    const float* lpos     = (const float*)d_in[3];
    const float* ppos     = (const float*)d_in[4];
    const float* pa_qkv_w = (const float*)d_in[5];
    const float* pa_qkv_b = (const float*)d_in[6];
    const float* pa_out_w = (const float*)d_in[7];
    const float* pa_out_b = (const float*)d_in[8];
    const float* proj_w   = (const float*)d_in[9];
    const float* proj_b   = (const float*)d_in[10];
    const float* lqkv_w   = (const float*)d_in[11];
    const float* lqkv_b   = (const float*)d_in[12];
    const float* lout_w   = (const float*)d_in[13];
    const float* lout_b   = (const float*)d_in[14];
    const float* ln1w     = (const float*)d_in[15];
    const float* ln1b     = (const float*)d_in[16];
    const float* ln2w     = (const float*)d_in[17];
    const float* ln2b     = (const float*)d_in[18];
    const float* ff1w     = (const float*)d_in[19];
    const float* ff1b     = (const float*)d_in[20];
    const float* ff2w     = (const float*)d_in[21];
    const float* ff2b     = (const float*)d_in[22];
    const float* lnfw     = (const float*)d_in[23];
    const float* lnfb     = (const float*)d_in[24];
    float* out = (float*)d_out;

    cudaFuncSetAttribute(mma_gemm<0>, cudaFuncAttributeMaxDynamicSharedMemorySize, GSMEM);
    cudaFuncSetAttribute(mma_gemm<1>, cudaFuncAttributeMaxDynamicSharedMemorySize, GSMEM);

    float *emb, *qkvb, *ctxb, *pr, *h, *hn, *ffb;
    __nv_bfloat16 *ahi, *alo, *whi, *wlo;
    cudaGetSymbolAddress((void**)&emb,  g_emb);
    cudaGetSymbolAddress((void**)&qkvb, g_qkv);
    cudaGetSymbolAddress((void**)&ctxb, g_ctx);
    cudaGetSymbolAddress((void**)&pr,   g_pr);
    cudaGetSymbolAddress((void**)&h,    g_h);
    cudaGetSymbolAddress((void**)&hn,   g_hn);
    cudaGetSymbolAddress((void**)&ffb,  g_ff);
    cudaGetSymbolAddress((void**)&ahi,  g_ahi);
    cudaGetSymbolAddress((void**)&alo,  g_alo);
    cudaGetSymbolAddress((void**)&whi,  g_whi);
    cudaGetSymbolAddress((void**)&wlo,  g_wlo);

    // 1) embeddings (masked)
    embed_kernel<<<P_ * L_, 256>>>(tokens, lengths, byte_emb, lpos, emb);

    // 2) local qkv: [32768,512] @ [1536,512]^T
    run_gemm(emb, pa_qkv_w, pa_qkv_b, nullptr, qkvb, P_ * L_, 3 * E_, E_, 0, ahi, alo, whi, wlo);

    // 3) per-patch attention
    local_attn_kernel<<<dim3(P_, HPA_), 128>>>(qkvb, lengths, ctxb);

    // 4) local out-proj -> reuse emb as attn output
    run_gemm(ctxb, pa_out_w, pa_out_b, nullptr, emb, P_ * L_, E_, E_, 0, ahi, alo, whi, wlo);

    // 5) masked mean -> patch_repr
    meanpool_kernel<<<P_, 512>>>(emb, lengths, pr);

    // 6) project + patch positions -> h
    run_gemm(pr, proj_w, proj_b, ppos, h, P_, D_, E_, 0, ahi, alo, whi, wlo);

    // 7) transformer layers
    for (int i = 0; i < NL_; i++) {
        ln_kernel<<<P_, 256>>>(h, ln1w + (size_t)i * D_, ln1b + (size_t)i * D_, hn);
        run_gemm(hn, lqkv_w + (size_t)i * 3 * D_ * D_, lqkv_b + (size_t)i * 3 * D_,
                 nullptr, qkvb, P_, 3 * D_, D_, 0, ahi, alo, whi, wlo);
        trans_attn_kernel<<<dim3(128, HTR_), 128>>>(qkvb, ctxb);
        run_gemm(ctxb, lout_w + (size_t)i * D_ * D_, lout_b + (size_t)i * D_,
                 h, h, P_, D_, D_, 0, ahi, alo, whi, wlo);
        ln_kernel<<<P_, 256>>>(h, ln2w + (size_t)i * D_, ln2b + (size_t)i * D_, hn);
        run_gemm(hn, ff1w + (size_t)i * FF_ * D_, ff1b + (size_t)i * FF_,
                 nullptr, ffb, P_, FF_, D_, 1, ahi, alo, whi, wlo);
        run_gemm(ffb, ff2w + (size_t)i * D_ * FF_, ff2b + (size_t)i * D_,
                 h, h, P_, D_, FF_, 0, ahi, alo, whi, wlo);
    }

    // 8) final layernorm -> output
    ln_kernel<<<P_, 256>>>(h, lnfw, lnfb, out);
}

// round 14
// speedup vs baseline: 1.5977x; 1.5977x over previous
#include <cuda_runtime.h>
#include <cuda_bf16.h>
#include <cstdint>
#include <math.h>

#define P_   1024
#define L_   32
#define E_   512
#define D_   768
#define NL_  6
#define FF_  3072
#define HPA_ 4
#define HTR_ 8
#define DH_  96            // transformer head dim

typedef __nv_bfloat16 bf16;
typedef __nv_bfloat162 bf162;

// ---------------- scratch (device globals; no allocation allowed) ----------------
__device__ float g_qkv[P_ * L_ * 3 * E_];    // local qkv [32768,1536]; trans qkv [1024,2304]
__device__ float g_ctx[P_ * L_ * E_];        // local attn-out fp32; later ctxpad [8][1024][128]
__device__ float g_sc [P_ * L_ * E_];        // scores [8][1024][1024] (16.8M >= 8.4M)
__device__ float g_h  [P_ * D_];             // hidden (residual stream)

__device__ bf16 g_Ahi[P_ * L_ * E_], g_Alo[P_ * L_ * E_];     // big activations (emb / local ctx)
__device__ bf16 g_Bhi[P_ * D_],      g_Blo[P_ * D_];          // pr / hn / ctx2
__device__ bf16 g_Fhi[P_ * FF_],     g_Flo[P_ * FF_];         // ffn intermediate
__device__ bf16 g_Shi[HTR_ * P_ * P_], g_Slo[HTR_ * P_ * P_]; // softmax probs
__device__ bf16 g_Qhi[HTR_ * P_ * DH_], g_Qlo[HTR_ * P_ * DH_];
__device__ bf16 g_Khi[HTR_ * P_ * DH_], g_Klo[HTR_ * P_ * DH_];
__device__ bf16 g_Vhi[HTR_ * 128 * P_], g_Vlo[HTR_ * 128 * P_];  // V^T padded to 128 rows
__device__ bf16 g_whi[FF_ * D_], g_wlo[FF_ * D_];             // weight split scratch

// ---------------- helpers ----------------
__device__ __forceinline__ float gelu_exact(float x) {
    return 0.5f * x * (1.0f + erff(x * 0.70710678118654752440f));
}
__device__ __forceinline__ void split2(float x, bf16& h, bf16& l) {
    h = __float2bfloat16(x);
    l = __float2bfloat16(x - __bfloat162float(h));
}
__device__ __forceinline__ uint32_t smem_u32(const void* p) {
    uint32_t a;
    asm("{ .reg .u64 t; cvta.to.shared.u64 t, %1; cvt.u32.u64 %0, t; }" : "=r"(a) : "l"(p));
    return a;
}
__device__ __forceinline__ void cp16(uint32_t dst, const void* src) {
    asm volatile("cp.async.cg.shared.global [%0], [%1], 16;" :: "r"(dst), "l"(src));
}
__device__ __forceinline__ void cp_commit() {
    asm volatile("cp.async.commit_group;" ::: "memory");
}
__device__ __forceinline__ void ldsm4(uint32_t& r0, uint32_t& r1, uint32_t& r2, uint32_t& r3,
                                      uint32_t addr) {
    asm volatile("ldmatrix.sync.aligned.m8n8.x4.shared.b16 {%0,%1,%2,%3}, [%4];"
                 : "=r"(r0), "=r"(r1), "=r"(r2), "=r"(r3) : "r"(addr));
}
__device__ __forceinline__ void mma_bf16(float* c, const uint32_t* a, const uint32_t* b) {
    asm volatile(
        "mma.sync.aligned.m16n8k16.row.col.f32.bf16.bf16.f32 "
        "{%0,%1,%2,%3}, {%4,%5,%6,%7}, {%8,%9}, {%0,%1,%2,%3};"
        : "+f"(c[0]), "+f"(c[1]), "+f"(c[2]), "+f"(c[3])
        : "r"(a[0]), "r"(a[1]), "r"(a[2]), "r"(a[3]), "r"(b[0]), "r"(b[1]));
}

// ---------------- fp32 -> bf16 hi/lo split (weights only now) ----------------
__global__ void split_kernel(const float* __restrict__ x, bf16* __restrict__ hi,
                             bf16* __restrict__ lo, int n4) {
    int i = blockIdx.x * 256 + threadIdx.x;
    if (i >= n4) return;
    float4 v = reinterpret_cast<const float4*>(x)[i];
    bf16 h0, h1, h2, h3, l0, l1, l2, l3;
    split2(v.x, h0, l0); split2(v.y, h1, l1);
    split2(v.z, h2, l2); split2(v.w, h3, l3);
    bf162* hp = reinterpret_cast<bf162*>(hi);
    bf162* lp = reinterpret_cast<bf162*>(lo);
    hp[2 * i]     = bf162(h0, h1);
    hp[2 * i + 1] = bf162(h2, h3);
    lp[2 * i]     = bf162(l0, l1);
    lp[2 * i + 1] = bf162(l2, l3);
}

// ---------------- HMMA GEMM: C = epi(A@W^T + bias) (+Res), batched, hi/lo ----------------
// BM=BN=128, BK=32, 512 threads (4x4 warps, 32x32 each).
// OUT=0: fp32 to Cf. OUT=1: hi/lo bf16 to Chi/Clo. ACT=1: exact GELU before residual.
#define TPAD    40
#define TILE_B  (128 * TPAD * 2)     // 10240
#define STAGE_B (4 * TILE_B)         // 40960
#define GSMEM   (2 * STAGE_B)        // 81920

template<int ACT, int OUT>
__global__ void __launch_bounds__(512, 1)
mma_gemm(const bf16* __restrict__ Ahi, const bf16* __restrict__ Alo,
         const bf16* __restrict__ Whi, const bf16* __restrict__ Wlo,
         const float* __restrict__ bias, const float* __restrict__ Res,
         float* __restrict__ Cf, bf16* __restrict__ Chi, bf16* __restrict__ Clo,
         int lda, int ldb, int ldc, int K,
         long long sA, long long sB, long long sC) {
    extern __shared__ char smem[];
    uint32_t sb = smem_u32(smem);
    int tid = threadIdx.x, lane = tid & 31, warp = tid >> 5;
    int wm = warp >> 2, wn = warp & 3;
    int m0 = blockIdx.y * 128, n0 = blockIdx.x * 128;
    long long boff = (long long)blockIdx.z;
    Ahi += boff * sA; Alo += boff * sA;
    Whi += boff * sB; Wlo += boff * sB;
    size_t cbatch = (size_t)(boff * sC);

    float acc[2][4][4];
    #pragma unroll
    for (int mf = 0; mf < 2; mf++)
        #pragma unroll
        for (int nf = 0; nf < 4; nf++)
            #pragma unroll
            for (int q = 0; q < 4; q++) acc[mf][nf][q] = 0.0f;

    auto load_stage = [&](int s, int k0) {
        uint32_t base = sb + s * STAGE_B;
        int r = tid >> 2, c = tid & 3;
        uint32_t doff = (uint32_t)(r * 80 + c * 16);
        size_t aoff = (size_t)(m0 + r) * lda + k0 + c * 8;
        size_t woff = (size_t)(n0 + r) * ldb + k0 + c * 8;
        cp16(base + doff,              Ahi + aoff);
        cp16(base + TILE_B + doff,     Alo + aoff);
        cp16(base + 2 * TILE_B + doff, Whi + woff);
        cp16(base + 3 * TILE_B + doff, Wlo + woff);
        cp_commit();
    };

    auto compute_stage = [&](int s) {
        uint32_t base = sb + s * STAGE_B;
        #pragma unroll
        for (int ks = 0; ks < 2; ks++) {
            int kk = ks * 16;
            uint32_t ahi[2][4], alo[2][4];
            #pragma unroll
            for (int mf = 0; mf < 2; mf++) {
                int row = wm * 32 + mf * 16 + (lane & 15);
                int kc  = kk + ((lane >> 4) << 3);
                uint32_t off = (uint32_t)(row * 80 + kc * 2);
                ldsm4(ahi[mf][0], ahi[mf][1], ahi[mf][2], ahi[mf][3], base + off);
                ldsm4(alo[mf][0], alo[mf][1], alo[mf][2], alo[mf][3], base + TILE_B + off);
            }
            uint32_t bhi[4][2], blo[4][2];
            #pragma unroll
            for (int nq = 0; nq < 2; nq++) {
                int row = wn * 32 + nq * 16 + ((lane >> 4) << 3) + (lane & 7);
                int kc  = kk + (((lane >> 3) & 1) << 3);
                uint32_t off = (uint32_t)(row * 80 + kc * 2);
                uint32_t r0, r1, r2, r3;
                ldsm4(r0, r1, r2, r3, base + 2 * TILE_B + off);
                bhi[2 * nq][0] = r0; bhi[2 * nq][1] = r1;
                bhi[2 * nq + 1][0] = r2; bhi[2 * nq + 1][1] = r3;
                ldsm4(r0, r1, r2, r3, base + 3 * TILE_B + off);
                blo[2 * nq][0] = r0; blo[2 * nq][1] = r1;
                blo[2 * nq + 1][0] = r2; blo[2 * nq + 1][1] = r3;
            }
            #pragma unroll
            for (int mf = 0; mf < 2; mf++)
                #pragma unroll
                for (int nf = 0; nf < 4; nf++) {
                    mma_bf16(acc[mf][nf], ahi[mf], bhi[nf]);
                    mma_bf16(acc[mf][nf], ahi[mf], blo[nf]);
                    mma_bf16(acc[mf][nf], alo[mf], bhi[nf]);
                }
        }
    };

    int nk = K >> 5;
    load_stage(0, 0);
    for (int kt = 0; kt < nk; kt++) {
        if (kt + 1 < nk) {
            load_stage((kt + 1) & 1, (kt + 1) << 5);
            asm volatile("cp.async.wait_group 1;" ::: "memory");
        } else {
            asm volatile("cp.async.wait_group 0;" ::: "memory");
        }
        __syncthreads();
        compute_stage(kt & 1);
        __syncthreads();
    }

    #pragma unroll
    for (int mf = 0; mf < 2; mf++) {
        int rbase = m0 + wm * 32 + mf * 16 + (lane >> 2);
        #pragma unroll
        for (int nf = 0; nf < 4; nf++) {
            int cbase = n0 + wn * 32 + nf * 8 + (lane & 3) * 2;
            #pragma unroll
            for (int half = 0; half < 2; half++) {
                int m = rbase + half * 8;
                float2 v;
                v.x = acc[mf][nf][half * 2];
                v.y = acc[mf][nf][half * 2 + 1];
                if (bias) { v.x += bias[cbase]; v.y += bias[cbase + 1]; }
                if (ACT == 1) { v.x = gelu_exact(v.x); v.y = gelu_exact(v.y); }
                size_t idx = cbatch + (size_t)m * ldc + cbase;
                if (Res) {
                    const float2 rv = *reinterpret_cast<const float2*>(Res + (size_t)m * ldc + cbase);
                    v.x += rv.x; v.y += rv.y;
                }
                if (OUT == 0) {
                    *reinterpret_cast<float2*>(Cf + idx) = v;
                } else {
                    bf16 h0, h1, l0, l1;
                    split2(v.x, h0, l0); split2(v.y, h1, l1);
                    *reinterpret_cast<bf162*>(Chi + idx) = bf162(h0, h1);
                    *reinterpret_cast<bf162*>(Clo + idx) = bf162(l0, l1);
                }
            }
        }
    }
}

// ---------------- embedding + mask -> hi/lo ----------------
__global__ void embed_kernel(const int* __restrict__ tokens, const int* __restrict__ lengths,
                             const float* __restrict__ byte_emb, const float* __restrict__ lpos,
                             bf16* __restrict__ ohi, bf16* __restrict__ olo) {
    int pl = blockIdx.x;
    int p  = pl >> 5;
    int l  = pl & 31;
    int t  = threadIdx.x;
    bool valid = (l < lengths[p]);
    int tok = tokens[pl];
    const float* be = byte_emb + (size_t)tok * E_;
    const float* lp = lpos + (size_t)l * E_;
    size_t base = (size_t)pl * E_;
    #pragma unroll
    for (int e = t; e < E_; e += 256) {
        float v = valid ? (be[e] + lp[e]) : 0.0f;
        bf16 h, lo2;
        split2(v, h, lo2);
        ohi[base + e] = h; olo[base + e] = lo2;
    }
}

// ---------------- local (per-patch) attention: S=32, d=128, 4 heads -> hi/lo ctx ----------------
__global__ void __launch_bounds__(128)
local_attn_kernel(const float* __restrict__ qkv, const int* __restrict__ lengths,
                  bf16* __restrict__ chi, bf16* __restrict__ clo) {
    __shared__ float bufA[32][129];
    __shared__ float bufK[32][129];
    __shared__ float s[32][33];

    int p = blockIdx.x, h = blockIdx.y, t = threadIdx.x;
    int len = lengths[p];
    const float scale = 0.08838834764831845f;
    const float* base = qkv + (size_t)p * 32 * 1536 + h * 128;

    #pragma unroll 4
    for (int l = 0; l < 32; l++) {
        bufA[l][t] = base[(size_t)l * 1536 + t] * scale;
        bufK[l][t] = base[(size_t)l * 1536 + 512 + t];
    }
    __syncthreads();

    #pragma unroll
    for (int w = 0; w < 8; w++) {
        int idx = t + w * 128;
        int i = idx >> 5, j = idx & 31;
        float acc = 0.0f;
        #pragma unroll 8
        for (int kk = 0; kk < 128; kk++) acc = fmaf(bufA[i][kk], bufK[j][kk], acc);
        s[i][j] = (j < len) ? acc : -1e30f;
    }
    __syncthreads();

    if (t < 32) {
        float mx = -1e30f;
        #pragma unroll
        for (int j = 0; j < 32; j++) mx = fmaxf(mx, s[t][j]);
        float sum = 0.0f;
        #pragma unroll
        for (int j = 0; j < 32; j++) { float e = __expf(s[t][j] - mx); s[t][j] = e; sum += e; }
        float inv = 1.0f / sum;
        #pragma unroll
        for (int j = 0; j < 32; j++) s[t][j] *= inv;
    }
    __syncthreads();

    #pragma unroll 4
    for (int l = 0; l < 32; l++)
        bufA[l][t] = base[(size_t)l * 1536 + 1024 + t];
    __syncthreads();

    for (int l = 0; l < 32; l++) {
        float acc = 0.0f;
        #pragma unroll
        for (int j = 0; j < 32; j++) acc = fmaf(s[l][j], bufA[j][t], acc);
        bf16 hv, lv;
        split2(acc, hv, lv);
        size_t idx = (size_t)(p * 32 + l) * 512 + h * 128 + t;
        chi[idx] = hv; clo[idx] = lv;
    }
}

// ---------------- masked mean -> hi/lo ----------------
__global__ void meanpool_kernel(const float* __restrict__ attn_out, const int* __restrict__ lengths,
                                bf16* __restrict__ phi, bf16* __restrict__ plo) {
    int p = blockIdx.x, t = threadIdx.x;
    int len = lengths[p];
    const float* b = attn_out + (size_t)p * 32 * 512 + t;
    float acc = 0.0f;
    for (int l = 0; l < len; l++) acc += b[(size_t)l * 512];
    float v = acc / (float)len;
    bf16 h, lo2;
    split2(v, h, lo2);
    phi[(size_t)p * 512 + t] = h;
    plo[(size_t)p * 512 + t] = lo2;
}

// ---------------- layernorm over D=768 (OUT=0 fp32, OUT=1 hi/lo) ----------------
template<int OUT>
__global__ void ln_kernel(const float* __restrict__ x, const float* __restrict__ w,
                          const float* __restrict__ b, float* __restrict__ y,
                          bf16* __restrict__ yh, bf16* __restrict__ yl) {
    __shared__ float red[8];
    int m = blockIdx.x, t = threadIdx.x;
    const float* xr = x + (size_t)m * D_;
    float v0 = xr[t], v1 = xr[t + 256], v2 = xr[t + 512];

    float s = v0 + v1 + v2;
    #pragma unroll
    for (int o = 16; o; o >>= 1) s += __shfl_xor_sync(0xffffffffu, s, o);
    if ((t & 31) == 0) red[t >> 5] = s;
    __syncthreads();
    if (t < 8) {
        float v = red[t];
        #pragma unroll
        for (int o = 4; o; o >>= 1) v += __shfl_xor_sync(0xffu, v, o);
        if (t == 0) red[0] = v;
    }
    __syncthreads();
    float mu = red[0] * (1.0f / D_);
    __syncthreads();

    float d0 = v0 - mu, d1 = v1 - mu, d2 = v2 - mu;
    float sq = d0 * d0 + d1 * d1 + d2 * d2;
    #pragma unroll
    for (int o = 16; o; o >>= 1) sq += __shfl_xor_sync(0xffffffffu, sq, o);
    if ((t & 31) == 0) red[t >> 5] = sq;
    __syncthreads();
    if (t < 8) {
        float v = red[t];
        #pragma unroll
        for (int o = 4; o; o >>= 1) v += __shfl_xor_sync(0xffu, v, o);
        if (t == 0) red[0] = v;
    }
    __syncthreads();
    float rstd = rsqrtf(red[0] * (1.0f / D_) + 1e-5f);

    size_t base = (size_t)m * D_;
    #pragma unroll
    for (int k = 0; k < 3; k++) {
        int e = t + k * 256;
        float dv = (k == 0 ? d0 : (k == 1 ? d1 : d2));
        float out = dv * rstd * w[e] + b[e];
        if (OUT == 0) y[base + e] = out;
        else {
            bf16 h, lo2;
            split2(out, h, lo2);
            yh[base + e] = h; yl[base + e] = lo2;
        }
    }
}

// ---------------- transformer attention prep: Q,K hi/lo + V^T(padded) hi/lo ----------------
__global__ void prep_attn_kernel(const float* __restrict__ qkv,
                                 bf16* __restrict__ qh, bf16* __restrict__ ql,
                                 bf16* __restrict__ kh, bf16* __restrict__ kl,
                                 bf16* __restrict__ vh, bf16* __restrict__ vl) {
    int m = blockIdx.x, t = threadIdx.x;
    const float scale = 0.10206207261596575f;   // 1/sqrt(96)
    const float* row = qkv + (size_t)m * 2304;
    for (int u = t; u < 768; u += 256) {
        int h = u / 96, d = u - h * 96;
        size_t qidx = (size_t)(h * P_ + m) * DH_ + d;
        bf16 hh, ll;
        split2(row[u] * scale, hh, ll);
        qh[qidx] = hh; ql[qidx] = ll;
        split2(row[768 + u], hh, ll);
        kh[qidx] = hh; kl[qidx] = ll;
        // V transposed: vt[h][d][m]
        size_t vidx = (size_t)h * 128 * P_ + (size_t)d * P_ + m;
        split2(row[1536 + u], hh, ll);
        vh[vidx] = hh; vl[vidx] = ll;
    }
    // zero the pad rows (d = 96..127) for this column m
    if (t < 256) {
        for (int u = t; u < 8 * 32; u += 256) {
            int h = u >> 5, d = 96 + (u & 31);
            size_t vidx = (size_t)h * 128 * P_ + (size_t)d * P_ + m;
            vh[vidx] = __float2bfloat16(0.0f);
            vl[vidx] = __float2bfloat16(0.0f);
        }
    }
}

// ---------------- row softmax: scores [8][1024][1024] fp32 -> probs hi/lo ----------------
__global__ void __launch_bounds__(256)
softmax_kernel(const float* __restrict__ sc, bf16* __restrict__ ph, bf16* __restrict__ pl) {
    __shared__ float red[8];
    int r = blockIdx.x;              // 0..8191 (h*1024+m)
    int t = threadIdx.x;
    const float4* row = reinterpret_cast<const float4*>(sc + (size_t)r * 1024);
    float4 v = row[t];
    float mx = fmaxf(fmaxf(v.x, v.y), fmaxf(v.z, v.w));
    #pragma unroll
    for (int o = 16; o; o >>= 1) mx = fmaxf(mx, __shfl_xor_sync(0xffffffffu, mx, o));
    if ((t & 31) == 0) red[t >> 5] = mx;
    __syncthreads();
    if (t < 8) {
        float z = red[t];
        #pragma unroll
        for (int o = 4; o; o >>= 1) z = fmaxf(z, __shfl_xor_sync(0xffu, z, o));
        if (t == 0) red[0] = z;
    }
    __syncthreads();
    mx = red[0];
    __syncthreads();
    float e0 = __expf(v.x - mx), e1 = __expf(v.y - mx);
    float e2 = __expf(v.z - mx), e3 = __expf(v.w - mx);
    float s = e0 + e1 + e2 + e3;
    #pragma unroll
    for (int o = 16; o; o >>= 1) s += __shfl_xor_sync(0xffffffffu, s, o);
    if ((t & 31) == 0) red[t >> 5] = s;
    __syncthreads();
    if (t < 8) {
        float z = red[t];
        #pragma unroll
        for (int o = 4; o; o >>= 1) z += __shfl_xor_sync(0xffu, z, o);
        if (t == 0) red[0] = z;
    }
    __syncthreads();
    float inv = 1.0f / red[0];
    e0 *= inv; e1 *= inv; e2 *= inv; e3 *= inv;
    bf16 h0, h1, h2, h3, l0, l1, l2, l3;
    split2(e0, h0, l0); split2(e1, h1, l1);
    split2(e2, h2, l2); split2(e3, h3, l3);
    size_t base = (size_t)r * 1024 + t * 4;
    *reinterpret_cast<bf162*>(ph + base)     = bf162(h0, h1);
    *reinterpret_cast<bf162*>(ph + base + 2) = bf162(h2, h3);
    *reinterpret_cast<bf162*>(pl + base)     = bf162(l0, l1);
    *reinterpret_cast<bf162*>(pl + base + 2) = bf162(l2, l3);
}

// ---------------- repack ctxpad [8][1024][128] fp32 -> ctx hi/lo [1024][768] ----------------
__global__ void repack_kernel(const float* __restrict__ cp,
                              bf16* __restrict__ ch, bf16* __restrict__ cl) {
    int m = blockIdx.x, t = threadIdx.x;
    for (int u = t; u < 768; u += 256) {
        int h = u / 96, d = u - h * 96;
        float v = cp[(size_t)h * P_ * 128 + (size_t)m * 128 + d];
        bf16 hh, ll;
        split2(v, hh, ll);
        ch[(size_t)m * 768 + u] = hh;
        cl[(size_t)m * 768 + u] = ll;
    }
}

// ---------------- host-side GEMM wrappers ----------------
static void gemm_go(const bf16* Ah, const bf16* Al, const bf16* Wh, const bf16* Wl,
                    const float* bias, const float* Res,
                    float* Cf, bf16* Ch, bf16* Cl,
                    int M, int N, int K, int lda, int ldb, int ldc,
                    long long sA, long long sB, long long sC, int nb,
                    int act, int outm) {
    dim3 grid(N / 128, M / 128, nb), block(512);
    if (act == 0 && outm == 0)
        mma_gemm<0, 0><<<grid, block, GSMEM>>>(Ah, Al, Wh, Wl, bias, Res, Cf, Ch, Cl,
                                               lda, ldb, ldc, K, sA, sB, sC);
    else if (act == 1 && outm == 1)
        mma_gemm<1, 1><<<grid, block, GSMEM>>>(Ah, Al, Wh, Wl, bias, Res, Cf, Ch, Cl,
                                               lda, ldb, ldc, K, sA, sB, sC);
    else if (act == 0 && outm == 1)
        mma_gemm<0, 1><<<grid, block, GSMEM>>>(Ah, Al, Wh, Wl, bias, Res, Cf, Ch, Cl,
                                               lda, ldb, ldc, K, sA, sB, sC);
    else
        mma_gemm<1, 0><<<grid, block, GSMEM>>>(Ah, Al, Wh, Wl, bias, Res, Cf, Ch, Cl,
                                               lda, ldb, ldc, K, sA, sB, sC);
}

// weight-splitting gemm (A pre-split; W fp32 -> split scratch)
static void gemm_w(const bf16* Ah, const bf16* Al, const float* W,
                   const float* bias, const float* Res,
                   float* Cf, bf16* Ch, bf16* Cl,
                   int M, int N, int K, int ldc, int act, int outm,
                   bf16* whi, bf16* wlo) {
    int nw4 = (N * K) / 4;
    split_kernel<<<(nw4 + 255) / 256, 256>>>(W, whi, wlo, nw4);
    gemm_go(Ah, Al, whi, wlo, bias, Res, Cf, Ch, Cl, M, N, K, K, K, ldc, 0, 0, 0, 1, act, outm);
}

extern "C" void kernel_launch(void* const* d_in, const int* in_sizes, int n_in,
                              void* d_out, int out_size) {
    const int*   tokens   = (const int*)d_in[0];
    const int*   lengths  = (const int*)d_in[1];
    const float* byte_emb = (const float*)d_in[2];
    const float* lpos     = (const float*)d_in[3];
    const float* ppos     = (const float*)d_in[4];
    const float* pa_qkv_w = (const float*)d_in[5];
    const float* pa_qkv_b = (const float*)d_in[6];
    const float* pa_out_w = (const float*)d_in[7];
    const float* pa_out_b = (const float*)d_in[8];
    const float* proj_w   = (const float*)d_in[9];
    const float* proj_b   = (const float*)d_in[10];
    const float* lqkv_w   = (const float*)d_in[11];
    const float* lqkv_b   = (const float*)d_in[12];
    const float* lout_w   = (const float*)d_in[13];
    const float* lout_b   = (const float*)d_in[14];
    const float* ln1w     = (const float*)d_in[15];
    const float* ln1b     = (const float*)d_in[16];
    const float* ln2w     = (const float*)d_in[17];
    const float* ln2b     = (const float*)d_in[18];
    const float* ff1w     = (const float*)d_in[19];
    const float* ff1b     = (const float*)d_in[20];
    const float* ff2w     = (const float*)d_in[21];
    const float* ff2b     = (const float*)d_in[22];
    const float* lnfw     = (const float*)d_in[23];
    const float* lnfb     = (const float*)d_in[24];
    float* out = (float*)d_out;

    cudaFuncSetAttribute(mma_gemm<0, 0>, cudaFuncAttributeMaxDynamicSharedMemorySize, GSMEM);
    cudaFuncSetAttribute(mma_gemm<0, 1>, cudaFuncAttributeMaxDynamicSharedMemorySize, GSMEM);
    cudaFuncSetAttribute(mma_gemm<1, 0>, cudaFuncAttributeMaxDynamicSharedMemorySize, GSMEM);
    cudaFuncSetAttribute(mma_gemm<1, 1>, cudaFuncAttributeMaxDynamicSharedMemorySize, GSMEM);

    float *qkvb, *ctxf, *scf, *h;
    bf16 *Ahi, *Alo, *Bhi, *Blo, *Fhi, *Flo, *Shi, *Slo;
    bf16 *Qhi, *Qlo, *Khi, *Klo, *Vhi, *Vlo, *whi, *wlo;
    cudaGetSymbolAddress((void**)&qkvb, g_qkv);
    cudaGetSymbolAddress((void**)&ctxf, g_ctx);
    cudaGetSymbolAddress((void**)&scf,  g_sc);
    cudaGetSymbolAddress((void**)&h,    g_h);
    cudaGetSymbolAddress((void**)&Ahi,  g_Ahi);  cudaGetSymbolAddress((void**)&Alo, g_Alo);
    cudaGetSymbolAddress((void**)&Bhi,  g_Bhi);  cudaGetSymbolAddress((void**)&Blo, g_Blo);
    cudaGetSymbolAddress((void**)&Fhi,  g_Fhi);  cudaGetSymbolAddress((void**)&Flo, g_Flo);
    cudaGetSymbolAddress((void**)&Shi,  g_Shi);  cudaGetSymbolAddress((void**)&Slo, g_Slo);
    cudaGetSymbolAddress((void**)&Qhi,  g_Qhi);  cudaGetSymbolAddress((void**)&Qlo, g_Qlo);
    cudaGetSymbolAddress((void**)&Khi,  g_Khi);  cudaGetSymbolAddress((void**)&Klo, g_Klo);
    cudaGetSymbolAddress((void**)&Vhi,  g_Vhi);  cudaGetSymbolAddress((void**)&Vlo, g_Vlo);
    cudaGetSymbolAddress((void**)&whi,  g_whi);  cudaGetSymbolAddress((void**)&wlo, g_wlo);

    // 1) embeddings (masked) -> hi/lo
    embed_kernel<<<P_ * L_, 256>>>(tokens, lengths, byte_emb, lpos, Ahi, Alo);

    // 2) local qkv: [32768,512] @ [1536,512]^T -> fp32
    gemm_w(Ahi, Alo, pa_qkv_w, pa_qkv_b, nullptr, qkvb, nullptr, nullptr,
           P_ * L_, 3 * E_, E_, 3 * E_, 0, 0, whi, wlo);

    // 3) per-patch attention -> ctx hi/lo (reuses A buffers)
    local_attn_kernel<<<dim3(P_, HPA_), 128>>>(qkvb, lengths, Ahi, Alo);

    // 4) local out-proj -> fp32 attn-out
    gemm_w(Ahi, Alo, pa_out_w, pa_out_b, nullptr, ctxf, nullptr, nullptr,
           P_ * L_, E_, E_, E_, 0, 0, whi, wlo);

    // 5) masked mean -> pr hi/lo
    meanpool_kernel<<<P_, 512>>>(ctxf, lengths, Bhi, Blo);

    // 6) project + patch positions -> h
    gemm_w(Bhi, Blo, proj_w, proj_b, ppos, h, nullptr, nullptr,
           P_, D_, E_, D_, 0, 0, whi, wlo);

    // 7) transformer layers
    for (int i = 0; i < NL_; i++) {
        ln_kernel<1><<<P_, 256>>>(h, ln1w + (size_t)i * D_, ln1b + (size_t)i * D_,
                                  nullptr, Bhi, Blo);
        gemm_w(Bhi, Blo, lqkv_w + (size_t)i * 3 * D_ * D_, lqkv_b + (size_t)i * 3 * D_,
               nullptr, qkvb, nullptr, nullptr, P_, 3 * D_, D_, 3 * D_, 0, 0, whi, wlo);
        prep_attn_kernel<<<P_, 256>>>(qkvb, Qhi, Qlo, Khi, Klo, Vhi, Vlo);
        // scores: per-head [1024,1024] = Q @ K^T, K=96
        gemm_go(Qhi, Qlo, Khi, Klo, nullptr, nullptr, scf, nullptr, nullptr,
                P_, P_, DH_, DH_, DH_, P_,
                (long long)P_ * DH_, (long long)P_ * DH_, (long long)P_ * P_, HTR_, 0, 0);
        softmax_kernel<<<HTR_ * P_, 256>>>(scf, Shi, Slo);
        // ctx(padded): per-head [1024,128] = S @ VT^T, K=1024
        gemm_go(Shi, Slo, Vhi, Vlo, nullptr, nullptr, ctxf, nullptr, nullptr,
                P_, 128, P_, P_, P_, 128,
                (long long)P_ * P_, (long long)128 * P_, (long long)P_ * 128, HTR_, 0, 0);
        repack_kernel<<<P_, 256>>>(ctxf, Bhi, Blo);
        gemm_w(Bhi, Blo, lout_w + (size_t)i * D_ * D_, lout_b + (size_t)i * D_,
               h, h, nullptr, nullptr, P_, D_, D_, D_, 0, 0, whi, wlo);
        ln_kernel<1><<<P_, 256>>>(h, ln2w + (size_t)i * D_, ln2b + (size_t)i * D_,
                                  nullptr, Bhi, Blo);
        gemm_w(Bhi, Blo, ff1w + (size_t)i * FF_ * D_, ff1b + (size_t)i * FF_,
               nullptr, nullptr, Fhi, Flo, P_, FF_, D_, FF_, 1, 1, whi, wlo);
        gemm_w(Fhi, Flo, ff2w + (size_t)i * D_ * FF_, ff2b + (size_t)i * D_,
               h, h, nullptr, nullptr, P_, D_, FF_, D_, 0, 0, whi, wlo);
    }

    // 8) final layernorm -> output
    ln_kernel<0><<<P_, 256>>>(h, lnfw, lnfb, out, nullptr, nullptr);
}

// round 15
// speedup vs baseline: 2.0331x; 1.2725x over previous
#include <cuda_runtime.h>
#include <cuda_bf16.h>
#include <cstdint>
#include <math.h>

#define P_   1024
#define L_   32
#define E_   512
#define D_   768
#define NL_  6
#define FF_  3072
#define HPA_ 4
#define HTR_ 8
#define DH_  96            // transformer head dim (padded to 128 for GEMM)

typedef __nv_bfloat16 bf16;
typedef __nv_bfloat162 bf162;

// ---------------- scratch (device globals; no allocation allowed) ----------------
__device__ float g_qkv[P_ * L_ * 3 * E_];    // local qkv [32768,1536]; trans qkv [1024,2304]
__device__ float g_ctx[P_ * L_ * E_];        // local attn-out fp32; later ctxpad [8][1024][128]
__device__ float g_sc [P_ * L_ * E_];        // scores [8][1024][1024]
__device__ float g_h  [P_ * D_];             // hidden (residual stream)

__device__ bf16 g_Ahi[P_ * L_ * E_], g_Alo[P_ * L_ * E_];
__device__ bf16 g_Bhi[P_ * D_],      g_Blo[P_ * D_];
__device__ bf16 g_Fhi[P_ * FF_],     g_Flo[P_ * FF_];
__device__ bf16 g_Shi[HTR_ * P_ * P_], g_Slo[HTR_ * P_ * P_];
__device__ bf16 g_Qhi[HTR_ * P_ * 128], g_Qlo[HTR_ * P_ * 128];   // padded K-dim 128
__device__ bf16 g_Khi[HTR_ * P_ * 128], g_Klo[HTR_ * P_ * 128];
__device__ bf16 g_Vhi[HTR_ * 128 * P_], g_Vlo[HTR_ * 128 * P_];   // V^T padded to 128 rows
__device__ bf16 g_whi[FF_ * D_], g_wlo[FF_ * D_];

// ---------------- helpers ----------------
__device__ __forceinline__ float gelu_exact(float x) {
    return 0.5f * x * (1.0f + erff(x * 0.70710678118654752440f));
}
__device__ __forceinline__ void split2(float x, bf16& h, bf16& l) {
    h = __float2bfloat16(x);
    l = __float2bfloat16(x - __bfloat162float(h));
}
__device__ __forceinline__ uint32_t smem_u32(const void* p) {
    uint32_t a;
    asm("{ .reg .u64 t; cvta.to.shared.u64 t, %1; cvt.u32.u64 %0, t; }" : "=r"(a) : "l"(p));
    return a;
}
__device__ __forceinline__ void cp16(uint32_t dst, const void* src) {
    asm volatile("cp.async.cg.shared.global [%0], [%1], 16;" :: "r"(dst), "l"(src));
}
__device__ __forceinline__ void cp_commit() {
    asm volatile("cp.async.commit_group;" ::: "memory");
}
__device__ __forceinline__ void ldsm4(uint32_t& r0, uint32_t& r1, uint32_t& r2, uint32_t& r3,
                                      uint32_t addr) {
    asm volatile("ldmatrix.sync.aligned.m8n8.x4.shared.b16 {%0,%1,%2,%3}, [%4];"
                 : "=r"(r0), "=r"(r1), "=r"(r2), "=r"(r3) : "r"(addr));
}
__device__ __forceinline__ void mma_bf16(float* c, const uint32_t* a, const uint32_t* b) {
    asm volatile(
        "mma.sync.aligned.m16n8k16.row.col.f32.bf16.bf16.f32 "
        "{%0,%1,%2,%3}, {%4,%5,%6,%7}, {%8,%9}, {%0,%1,%2,%3};"
        : "+f"(c[0]), "+f"(c[1]), "+f"(c[2]), "+f"(c[3])
        : "r"(a[0]), "r"(a[1]), "r"(a[2]), "r"(a[3]), "r"(b[0]), "r"(b[1]));
}

// ---------------- fp32 -> bf16 hi/lo split (weights) ----------------
__global__ void split_kernel(const float* __restrict__ x, bf16* __restrict__ hi,
                             bf16* __restrict__ lo, int n4) {
    int i = blockIdx.x * 256 + threadIdx.x;
    if (i >= n4) return;
    float4 v = reinterpret_cast<const float4*>(x)[i];
    bf16 h0, h1, h2, h3, l0, l1, l2, l3;
    split2(v.x, h0, l0); split2(v.y, h1, l1);
    split2(v.z, h2, l2); split2(v.w, h3, l3);
    bf162* hp = reinterpret_cast<bf162*>(hi);
    bf162* lp = reinterpret_cast<bf162*>(lo);
    hp[2 * i]     = bf162(h0, h1);
    hp[2 * i + 1] = bf162(h2, h3);
    lp[2 * i]     = bf162(l0, l1);
    lp[2 * i + 1] = bf162(l2, l3);
}

// ---------------- HMMA GEMM: C = epi(A@W^T + bias) (+Res), batched, hi/lo ----------------
// BMxBN = BMx128, BK=64, BM/32 x 4 warp grid (32x32 per warp). Row stride 144 B.
#define RS 144
template<int BM> struct GC {
    static constexpr int AOFF = BM * RS;          // Alo
    static constexpr int BOFF = 2 * BM * RS;      // Bhi
    static constexpr int B2   = BOFF + 128 * RS;  // Blo
    static constexpr int STG  = 2 * BM * RS + 2 * 128 * RS;
    static constexpr int SMEM = 2 * STG;
};

template<int ACT, int OUT, int BM>
__global__ void __launch_bounds__(BM * 4, 1)
mma_gemm(const bf16* __restrict__ Ahi, const bf16* __restrict__ Alo,
         const bf16* __restrict__ Whi, const bf16* __restrict__ Wlo,
         const float* __restrict__ bias, const float* __restrict__ Res,
         float* __restrict__ Cf, bf16* __restrict__ Chi, bf16* __restrict__ Clo,
         int lda, int ldb, int ldc, int K,
         long long sA, long long sB, long long sC) {
    extern __shared__ char smem[];
    uint32_t sb = smem_u32(smem);
    constexpr int T = BM * 4;
    int tid = threadIdx.x, lane = tid & 31, warp = tid >> 5;
    int wm = warp >> 2, wn = warp & 3;
    int m0 = blockIdx.y * BM, n0 = blockIdx.x * 128;
    long long boff = (long long)blockIdx.z;
    Ahi += boff * sA; Alo += boff * sA;
    Whi += boff * sB; Wlo += boff * sB;
    size_t cbatch = (size_t)(boff * sC);

    float acc[2][4][4];
    #pragma unroll
    for (int mf = 0; mf < 2; mf++)
        #pragma unroll
        for (int nf = 0; nf < 4; nf++)
            #pragma unroll
            for (int q = 0; q < 4; q++) acc[mf][nf][q] = 0.0f;

    auto load_stage = [&](int s, int k0) {
        uint32_t base = sb + s * GC<BM>::STG;
        #pragma unroll
        for (int u = tid; u < BM * 8; u += T) {
            int r = u >> 3, c = u & 7;
            uint32_t doff = (uint32_t)(r * RS + c * 16);
            size_t aoff = (size_t)(m0 + r) * lda + k0 + c * 8;
            cp16(base + doff,                 Ahi + aoff);
            cp16(base + GC<BM>::AOFF + doff,  Alo + aoff);
        }
        #pragma unroll
        for (int u = tid; u < 1024; u += T) {
            int r = u >> 3, c = u & 7;
            uint32_t doff = (uint32_t)(r * RS + c * 16);
            size_t woff = (size_t)(n0 + r) * ldb + k0 + c * 8;
            cp16(base + GC<BM>::BOFF + doff, Whi + woff);
            cp16(base + GC<BM>::B2 + doff,   Wlo + woff);
        }
        cp_commit();
    };

    auto compute_stage = [&](int s) {
        uint32_t base = sb + s * GC<BM>::STG;
        #pragma unroll
        for (int ks = 0; ks < 4; ks++) {
            int kk = ks * 16;
            uint32_t ahi[2][4], alo[2][4];
            #pragma unroll
            for (int mf = 0; mf < 2; mf++) {
                int row = wm * 32 + mf * 16 + (lane & 15);
                int kc  = kk + ((lane >> 4) << 3);
                uint32_t off = (uint32_t)(row * RS + kc * 2);
                ldsm4(ahi[mf][0], ahi[mf][1], ahi[mf][2], ahi[mf][3], base + off);
                ldsm4(alo[mf][0], alo[mf][1], alo[mf][2], alo[mf][3],
                      base + GC<BM>::AOFF + off);
            }
            uint32_t bhi[4][2], blo[4][2];
            #pragma unroll
            for (int nq = 0; nq < 2; nq++) {
                int row = wn * 32 + nq * 16 + ((lane >> 4) << 3) + (lane & 7);
                int kc  = kk + (((lane >> 3) & 1) << 3);
                uint32_t off = (uint32_t)(row * RS + kc * 2);
                uint32_t r0, r1, r2, r3;
                ldsm4(r0, r1, r2, r3, base + GC<BM>::BOFF + off);
                bhi[2 * nq][0] = r0; bhi[2 * nq][1] = r1;
                bhi[2 * nq + 1][0] = r2; bhi[2 * nq + 1][1] = r3;
                ldsm4(r0, r1, r2, r3, base + GC<BM>::B2 + off);
                blo[2 * nq][0] = r0; blo[2 * nq][1] = r1;
                blo[2 * nq + 1][0] = r2; blo[2 * nq + 1][1] = r3;
            }
            #pragma unroll
            for (int mf = 0; mf < 2; mf++)
                #pragma unroll
                for (int nf = 0; nf < 4; nf++) {
                    mma_bf16(acc[mf][nf], ahi[mf], bhi[nf]);
                    mma_bf16(acc[mf][nf], ahi[mf], blo[nf]);
                    mma_bf16(acc[mf][nf], alo[mf], bhi[nf]);
                }
        }
    };

    int nk = K >> 6;
    load_stage(0, 0);
    for (int kt = 0; kt < nk; kt++) {
        if (kt + 1 < nk) {
            load_stage((kt + 1) & 1, (kt + 1) << 6);
            asm volatile("cp.async.wait_group 1;" ::: "memory");
        } else {
            asm volatile("cp.async.wait_group 0;" ::: "memory");
        }
        __syncthreads();
        compute_stage(kt & 1);
        __syncthreads();
    }

    #pragma unroll
    for (int mf = 0; mf < 2; mf++) {
        int rbase = m0 + wm * 32 + mf * 16 + (lane >> 2);
        #pragma unroll
        for (int nf = 0; nf < 4; nf++) {
            int cbase = n0 + wn * 32 + nf * 8 + (lane & 3) * 2;
            #pragma unroll
            for (int half = 0; half < 2; half++) {
                int m = rbase + half * 8;
                float2 v;
                v.x = acc[mf][nf][half * 2];
                v.y = acc[mf][nf][half * 2 + 1];
                if (bias) { v.x += bias[cbase]; v.y += bias[cbase + 1]; }
                if (ACT == 1) { v.x = gelu_exact(v.x); v.y = gelu_exact(v.y); }
                size_t idx = cbatch + (size_t)m * ldc + cbase;
                if (Res) {
                    const float2 rv = *reinterpret_cast<const float2*>(Res + (size_t)m * ldc + cbase);
                    v.x += rv.x; v.y += rv.y;
                }
                if (OUT == 0) {
                    *reinterpret_cast<float2*>(Cf + idx) = v;
                } else {
                    bf16 h0, h1, l0, l1;
                    split2(v.x, h0, l0); split2(v.y, h1, l1);
                    *reinterpret_cast<bf162*>(Chi + idx) = bf162(h0, h1);
                    *reinterpret_cast<bf162*>(Clo + idx) = bf162(l0, l1);
                }
            }
        }
    }
}

// ---------------- embedding + mask -> hi/lo ----------------
__global__ void embed_kernel(const int* __restrict__ tokens, const int* __restrict__ lengths,
                             const float* __restrict__ byte_emb, const float* __restrict__ lpos,
                             bf16* __restrict__ ohi, bf16* __restrict__ olo) {
    int pl = blockIdx.x;
    int p  = pl >> 5;
    int l  = pl & 31;
    int t  = threadIdx.x;
    bool valid = (l < lengths[p]);
    int tok = tokens[pl];
    const float* be = byte_emb + (size_t)tok * E_;
    const float* lp = lpos + (size_t)l * E_;
    size_t base = (size_t)pl * E_;
    #pragma unroll
    for (int e = t; e < E_; e += 256) {
        float v = valid ? (be[e] + lp[e]) : 0.0f;
        bf16 h, lo2;
        split2(v, h, lo2);
        ohi[base + e] = h; olo[base + e] = lo2;
    }
}

// ---------------- local attention: S=32, d=128, 4 heads (register-blocked) ----------------
__global__ void __launch_bounds__(128)
local_attn_kernel(const float* __restrict__ qkv, const int* __restrict__ lengths,
                  bf16* __restrict__ chi, bf16* __restrict__ clo) {
    __shared__ float bufQ[32][132];     // q scaled; later v
    __shared__ float bufK[32][132];
    __shared__ float st[32][36];        // st[j][i]: transposed scores (144B rows, 16B aligned)

    int p = blockIdx.x, h = blockIdx.y, t = threadIdx.x;
    int lane = t & 31, w = t >> 5, i0 = w * 8;
    int len = lengths[p];
    const float scale = 0.08838834764831845f;   // 1/sqrt(128)
    const float* base = qkv + (size_t)p * 32 * 1536 + h * 128;

    #pragma unroll 4
    for (int l = 0; l < 32; l++) {
        bufQ[l][t] = base[(size_t)l * 1536 + t] * scale;
        bufK[l][t] = base[(size_t)l * 1536 + 512 + t];
    }
    __syncthreads();

    // QK^T: warp w -> query rows i0..i0+7, lane -> key j
    {
        float acc[8] = {0, 0, 0, 0, 0, 0, 0, 0};
        #pragma unroll 8
        for (int kk = 0; kk < 32; kk++) {
            float4 kv = *reinterpret_cast<const float4*>(&bufK[lane][kk * 4]);
            #pragma unroll
            for (int r = 0; r < 8; r++) {
                float4 qv = *reinterpret_cast<const float4*>(&bufQ[i0 + r][kk * 4]);
                acc[r] += qv.x * kv.x + qv.y * kv.y + qv.z * kv.z + qv.w * kv.w;
            }
        }
        bool ok = lane < len;
        #pragma unroll
        for (int r = 0; r < 8; r++)
            st[lane][i0 + r] = ok ? acc[r] : -1e30f;
    }
    __syncthreads();

    // softmax: thread t<32 owns query row t (reads st column t)
    if (t < 32) {
        float mx = -1e30f;
        #pragma unroll
        for (int j = 0; j < 32; j++) mx = fmaxf(mx, st[j][t]);
        float sum = 0.0f;
        #pragma unroll
        for (int j = 0; j < 32; j++) { float e = __expf(st[j][t] - mx); st[j][t] = e; sum += e; }
        float inv = 1.0f / sum;
        #pragma unroll
        for (int j = 0; j < 32; j++) st[j][t] *= inv;
    }

    // reload v into bufQ
    __syncthreads();
    #pragma unroll 4
    for (int l = 0; l < 32; l++)
        bufQ[l][t] = base[(size_t)l * 1536 + 1024 + t];
    __syncthreads();

    // AV: thread t owns output column t, all 32 rows
    {
        float acc2[32];
        #pragma unroll
        for (int l = 0; l < 32; l++) acc2[l] = 0.0f;
        #pragma unroll 4
        for (int j = 0; j < 32; j++) {
            float vjt = bufQ[j][t];
            #pragma unroll
            for (int l4 = 0; l4 < 8; l4++) {
                float4 sv = *reinterpret_cast<const float4*>(&st[j][l4 * 4]);
                acc2[l4 * 4 + 0] = fmaf(sv.x, vjt, acc2[l4 * 4 + 0]);
                acc2[l4 * 4 + 1] = fmaf(sv.y, vjt, acc2[l4 * 4 + 1]);
                acc2[l4 * 4 + 2] = fmaf(sv.z, vjt, acc2[l4 * 4 + 2]);
                acc2[l4 * 4 + 3] = fmaf(sv.w, vjt, acc2[l4 * 4 + 3]);
            }
        }
        #pragma unroll 4
        for (int l = 0; l < 32; l++) {
            bf16 hv, lv;
            split2(acc2[l], hv, lv);
            size_t idx = (size_t)(p * 32 + l) * 512 + h * 128 + t;
            chi[idx] = hv; clo[idx] = lv;
        }
    }
}

// ---------------- masked mean -> hi/lo ----------------
__global__ void meanpool_kernel(const float* __restrict__ attn_out, const int* __restrict__ lengths,
                                bf16* __restrict__ phi, bf16* __restrict__ plo) {
    int p = blockIdx.x, t = threadIdx.x;
    int len = lengths[p];
    const float* b = attn_out + (size_t)p * 32 * 512 + t;
    float acc = 0.0f;
    for (int l = 0; l < len; l++) acc += b[(size_t)l * 512];
    float v = acc / (float)len;
    bf16 h, lo2;
    split2(v, h, lo2);
    phi[(size_t)p * 512 + t] = h;
    plo[(size_t)p * 512 + t] = lo2;
}

// ---------------- layernorm over D=768 (OUT=0 fp32, OUT=1 hi/lo) ----------------
template<int OUT>
__global__ void ln_kernel(const float* __restrict__ x, const float* __restrict__ w,
                          const float* __restrict__ b, float* __restrict__ y,
                          bf16* __restrict__ yh, bf16* __restrict__ yl) {
    __shared__ float red[8];
    int m = blockIdx.x, t = threadIdx.x;
    const float* xr = x + (size_t)m * D_;
    float v0 = xr[t], v1 = xr[t + 256], v2 = xr[t + 512];

    float s = v0 + v1 + v2;
    #pragma unroll
    for (int o = 16; o; o >>= 1) s += __shfl_xor_sync(0xffffffffu, s, o);
    if ((t & 31) == 0) red[t >> 5] = s;
    __syncthreads();
    if (t < 8) {
        float v = red[t];
        #pragma unroll
        for (int o = 4; o; o >>= 1) v += __shfl_xor_sync(0xffu, v, o);
        if (t == 0) red[0] = v;
    }
    __syncthreads();
    float mu = red[0] * (1.0f / D_);
    __syncthreads();

    float d0 = v0 - mu, d1 = v1 - mu, d2 = v2 - mu;
    float sq = d0 * d0 + d1 * d1 + d2 * d2;
    #pragma unroll
    for (int o = 16; o; o >>= 1) sq += __shfl_xor_sync(0xffffffffu, sq, o);
    if ((t & 31) == 0) red[t >> 5] = sq;
    __syncthreads();
    if (t < 8) {
        float v = red[t];
        #pragma unroll
        for (int o = 4; o; o >>= 1) v += __shfl_xor_sync(0xffu, v, o);
        if (t == 0) red[0] = v;
    }
    __syncthreads();
    float rstd = rsqrtf(red[0] * (1.0f / D_) + 1e-5f);

    size_t base = (size_t)m * D_;
    #pragma unroll
    for (int k = 0; k < 3; k++) {
        int e = t + k * 256;
        float dv = (k == 0 ? d0 : (k == 1 ? d1 : d2));
        float out = dv * rstd * w[e] + b[e];
        if (OUT == 0) y[base + e] = out;
        else {
            bf16 h, lo2;
            split2(out, h, lo2);
            yh[base + e] = h; yl[base + e] = lo2;
        }
    }
}

// ---------------- attention prep: Q,K hi/lo (K-dim padded to 128) + V^T hi/lo ----------------
__global__ void prep_attn_kernel(const float* __restrict__ qkv,
                                 bf16* __restrict__ qh, bf16* __restrict__ ql,
                                 bf16* __restrict__ kh, bf16* __restrict__ kl,
                                 bf16* __restrict__ vh, bf16* __restrict__ vl) {
    int m = blockIdx.x, t = threadIdx.x;
    const float scale = 0.10206207261596575f;   // 1/sqrt(96)
    const float* row = qkv + (size_t)m * 2304;
    for (int u = t; u < 768; u += 256) {
        int h = u / 96, d = u - h * 96;
        size_t qidx = ((size_t)h * P_ + m) * 128 + d;
        bf16 hh, ll;
        split2(row[u] * scale, hh, ll);
        qh[qidx] = hh; ql[qidx] = ll;
        split2(row[768 + u], hh, ll);
        kh[qidx] = hh; kl[qidx] = ll;
        size_t vidx = (size_t)h * 128 * P_ + (size_t)d * P_ + m;
        split2(row[1536 + u], hh, ll);
        vh[vidx] = hh; vl[vidx] = ll;
    }
    // zero pad cols 96..127 of q/k and rows 96..127 of v^T
    bf16 z = __float2bfloat16(0.0f);
    for (int u = t; u < 8 * 32; u += 256) {
        int h = u >> 5, d = 96 + (u & 31);
        size_t qidx = ((size_t)h * P_ + m) * 128 + d;
        qh[qidx] = z; ql[qidx] = z; kh[qidx] = z; kl[qidx] = z;
        size_t vidx = (size_t)h * 128 * P_ + (size_t)d * P_ + m;
        vh[vidx] = z; vl[vidx] = z;
    }
}

// ---------------- row softmax: scores fp32 -> probs hi/lo ----------------
__global__ void __launch_bounds__(256)
softmax_kernel(const float* __restrict__ sc, bf16* __restrict__ ph, bf16* __restrict__ pl) {
    __shared__ float red[8];
    int r = blockIdx.x;
    int t = threadIdx.x;
    const float4* row = reinterpret_cast<const float4*>(sc + (size_t)r * 1024);
    float4 v = row[t];
    float mx = fmaxf(fmaxf(v.x, v.y), fmaxf(v.z, v.w));
    #pragma unroll
    for (int o = 16; o; o >>= 1) mx = fmaxf(mx, __shfl_xor_sync(0xffffffffu, mx, o));
    if ((t & 31) == 0) red[t >> 5] = mx;
    __syncthreads();
    if (t < 8) {
        float z = red[t];
        #pragma unroll
        for (int o = 4; o; o >>= 1) z = fmaxf(z, __shfl_xor_sync(0xffu, z, o));
        if (t == 0) red[0] = z;
    }
    __syncthreads();
    mx = red[0];
    __syncthreads();
    float e0 = __expf(v.x - mx), e1 = __expf(v.y - mx);
    float e2 = __expf(v.z - mx), e3 = __expf(v.w - mx);
    float s = e0 + e1 + e2 + e3;
    #pragma unroll
    for (int o = 16; o; o >>= 1) s += __shfl_xor_sync(0xffffffffu, s, o);
    if ((t & 31) == 0) red[t >> 5] = s;
    __syncthreads();
    if (t < 8) {
        float z = red[t];
        #pragma unroll
        for (int o = 4; o; o >>= 1) z += __shfl_xor_sync(0xffu, z, o);
        if (t == 0) red[0] = z;
    }
    __syncthreads();
    float inv = 1.0f / red[0];
    e0 *= inv; e1 *= inv; e2 *= inv; e3 *= inv;
    bf16 h0, h1, h2, h3, l0, l1, l2, l3;
    split2(e0, h0, l0); split2(e1, h1, l1);
    split2(e2, h2, l2); split2(e3, h3, l3);
    size_t base = (size_t)r * 1024 + t * 4;
    *reinterpret_cast<bf162*>(ph + base)     = bf162(h0, h1);
    *reinterpret_cast<bf162*>(ph + base + 2) = bf162(h2, h3);
    *reinterpret_cast<bf162*>(pl + base)     = bf162(l0, l1);
    *reinterpret_cast<bf162*>(pl + base + 2) = bf162(l2, l3);
}

// ---------------- repack ctxpad [8][1024][128] fp32 -> ctx hi/lo [1024][768] ----------------
__global__ void repack_kernel(const float* __restrict__ cp,
                              bf16* __restrict__ ch, bf16* __restrict__ cl) {
    int m = blockIdx.x, t = threadIdx.x;
    for (int u = t; u < 768; u += 256) {
        int h = u / 96, d = u - h * 96;
        float v = cp[(size_t)h * P_ * 128 + (size_t)m * 128 + d];
        bf16 hh, ll;
        split2(v, hh, ll);
        ch[(size_t)m * 768 + u] = hh;
        cl[(size_t)m * 768 + u] = ll;
    }
}

// ---------------- host-side GEMM wrappers ----------------
static void gemm_go(const bf16* Ah, const bf16* Al, const bf16* Wh, const bf16* Wl,
                    const float* bias, const float* Res,
                    float* Cf, bf16* Ch, bf16* Cl,
                    int M, int N, int K, int lda, int ldb, int ldc,
                    long long sA, long long sB, long long sC, int nb,
                    int act, int outm, int bm) {
    if (bm == 64) {
        dim3 grid(N / 128, M / 64, nb);
        mma_gemm<0, 0, 64><<<grid, 256, GC<64>::SMEM>>>(Ah, Al, Wh, Wl, bias, Res,
                                                        Cf, Ch, Cl, lda, ldb, ldc, K, sA, sB, sC);
    } else {
        dim3 grid(N / 128, M / 128, nb);
        if (act == 1)
            mma_gemm<1, 1, 128><<<grid, 512, GC<128>::SMEM>>>(Ah, Al, Wh, Wl, bias, Res,
                                                              Cf, Ch, Cl, lda, ldb, ldc, K, sA, sB, sC);
        else
            mma_gemm<0, 0, 128><<<grid, 512, GC<128>::SMEM>>>(Ah, Al, Wh, Wl, bias, Res,
                                                              Cf, Ch, Cl, lda, ldb, ldc, K, sA, sB, sC);
    }
}

static void gemm_w(const bf16* Ah, const bf16* Al, const float* W,
                   const float* bias, const float* Res,
                   float* Cf, bf16* Ch, bf16* Cl,
                   int M, int N, int K, int ldc, int act, int outm, int bm,
                   bf16* whi, bf16* wlo) {
    int nw4 = (N * K) / 4;
    split_kernel<<<(nw4 + 255) / 256, 256>>>(W, whi, wlo, nw4);
    gemm_go(Ah, Al, whi, wlo, bias, Res, Cf, Ch, Cl, M, N, K, K, K, ldc,
            0, 0, 0, 1, act, outm, bm);
}

extern "C" void kernel_launch(void* const* d_in, const int* in_sizes, int n_in,
                              void* d_out, int out_size) {
    const int*   tokens   = (const int*)d_in[0];
    const int*   lengths  = (const int*)d_in[1];
    const float* byte_emb = (const float*)d_in[2];
    const float* lpos     = (const float*)d_in[3];
    const float* ppos     = (const float*)d_in[4];
    const float* pa_qkv_w = (const float*)d_in[5];
    const float* pa_qkv_b = (const float*)d_in[6];
    const float* pa_out_w = (const float*)d_in[7];
    const float* pa_out_b = (const float*)d_in[8];
    const float* proj_w   = (const float*)d_in[9];
    const float* proj_b   = (const float*)d_in[10];
    const float* lqkv_w   = (const float*)d_in[11];
    const float* lqkv_b   = (const float*)d_in[12];
    const float* lout_w   = (const float*)d_in[13];
    const float* lout_b   = (const float*)d_in[14];
    const float* ln1w     = (const float*)d_in[15];
    const float* ln1b     = (const float*)d_in[16];
    const float* ln2w     = (const float*)d_in[17];
    const float* ln2b     = (const float*)d_in[18];
    const float* ff1w     = (const float*)d_in[19];
    const float* ff1b     = (const float*)d_in[20];
    const float* ff2w     = (const float*)d_in[21];
    const float* ff2b     = (const float*)d_in[22];
    const float* lnfw     = (const float*)d_in[23];
    const float* lnfb     = (const float*)d_in[24];
    float* out = (float*)d_out;

    cudaFuncSetAttribute(mma_gemm<0, 0, 128>, cudaFuncAttributeMaxDynamicSharedMemorySize, GC<128>::SMEM);
    cudaFuncSetAttribute(mma_gemm<1, 1, 128>, cudaFuncAttributeMaxDynamicSharedMemorySize, GC<128>::SMEM);
    cudaFuncSetAttribute(mma_gemm<0, 0, 64>,  cudaFuncAttributeMaxDynamicSharedMemorySize, GC<64>::SMEM);

    float *qkvb, *ctxf, *scf, *h;
    bf16 *Ahi, *Alo, *Bhi, *Blo, *Fhi, *Flo, *Shi, *Slo;
    bf16 *Qhi, *Qlo, *Khi, *Klo, *Vhi, *Vlo, *whi, *wlo;
    cudaGetSymbolAddress((void**)&qkvb, g_qkv);
    cudaGetSymbolAddress((void**)&ctxf, g_ctx);
    cudaGetSymbolAddress((void**)&scf,  g_sc);
    cudaGetSymbolAddress((void**)&h,    g_h);
    cudaGetSymbolAddress((void**)&Ahi,  g_Ahi);  cudaGetSymbolAddress((void**)&Alo, g_Alo);
    cudaGetSymbolAddress((void**)&Bhi,  g_Bhi);  cudaGetSymbolAddress((void**)&Blo, g_Blo);
    cudaGetSymbolAddress((void**)&Fhi,  g_Fhi);  cudaGetSymbolAddress((void**)&Flo, g_Flo);
    cudaGetSymbolAddress((void**)&Shi,  g_Shi);  cudaGetSymbolAddress((void**)&Slo, g_Slo);
    cudaGetSymbolAddress((void**)&Qhi,  g_Qhi);  cudaGetSymbolAddress((void**)&Qlo, g_Qlo);
    cudaGetSymbolAddress((void**)&Khi,  g_Khi);  cudaGetSymbolAddress((void**)&Klo, g_Klo);
    cudaGetSymbolAddress((void**)&Vhi,  g_Vhi);  cudaGetSymbolAddress((void**)&Vlo, g_Vlo);
    cudaGetSymbolAddress((void**)&whi,  g_whi);  cudaGetSymbolAddress((void**)&wlo, g_wlo);

    // 1) embeddings (masked) -> hi/lo
    embed_kernel<<<P_ * L_, 256>>>(tokens, lengths, byte_emb, lpos, Ahi, Alo);

    // 2) local qkv
    gemm_w(Ahi, Alo, pa_qkv_w, pa_qkv_b, nullptr, qkvb, nullptr, nullptr,
           P_ * L_, 3 * E_, E_, 3 * E_, 0, 0, 128, whi, wlo);

    // 3) per-patch attention -> ctx hi/lo
    local_attn_kernel<<<dim3(P_, HPA_), 128>>>(qkvb, lengths, Ahi, Alo);

    // 4) local out-proj -> fp32
    gemm_w(Ahi, Alo, pa_out_w, pa_out_b, nullptr, ctxf, nullptr, nullptr,
           P_ * L_, E_, E_, E_, 0, 0, 128, whi, wlo);

    // 5) masked mean -> pr hi/lo
    meanpool_kernel<<<P_, 512>>>(ctxf, lengths, Bhi, Blo);

    // 6) project + patch positions -> h
    gemm_w(Bhi, Blo, proj_w, proj_b, ppos, h, nullptr, nullptr,
           P_, D_, E_, D_, 0, 0, 64, whi, wlo);

    // 7) transformer layers
    for (int i = 0; i < NL_; i++) {
        ln_kernel<1><<<P_, 256>>>(h, ln1w + (size_t)i * D_, ln1b + (size_t)i * D_,
                                  nullptr, Bhi, Blo);
        gemm_w(Bhi, Blo, lqkv_w + (size_t)i * 3 * D_ * D_, lqkv_b + (size_t)i * 3 * D_,
               nullptr, qkvb, nullptr, nullptr, P_, 3 * D_, D_, 3 * D_, 0, 0, 128, whi, wlo);
        prep_attn_kernel<<<P_, 256>>>(qkvb, Qhi, Qlo, Khi, Klo, Vhi, Vlo);
        // scores: per-head [1024,1024] = Q @ K^T, K=128 (zero-padded from 96)
        gemm_go(Qhi, Qlo, Khi, Klo, nullptr, nullptr, scf, nullptr, nullptr,
                P_, P_, 128, 128, 128, P_,
                (long long)P_ * 128, (long long)P_ * 128, (long long)P_ * P_, HTR_, 0, 0, 128);
        softmax_kernel<<<HTR_ * P_, 256>>>(scf, Shi, Slo);
        // ctx(padded): per-head [1024,128] = S @ VT^T, K=1024
        gemm_go(Shi, Slo, Vhi, Vlo, nullptr, nullptr, ctxf, nullptr, nullptr,
                P_, 128, P_, P_, P_, 128,
                (long long)P_ * P_, (long long)128 * P_, (long long)P_ * 128, HTR_, 0, 0, 64);
        repack_kernel<<<P_, 256>>>(ctxf, Bhi, Blo);
        gemm_w(Bhi, Blo, lout_w + (size_t)i * D_ * D_, lout_b + (size_t)i * D_,
               h, h, nullptr, nullptr, P_, D_, D_, D_, 0, 0, 64, whi, wlo);
        ln_kernel<1><<<P_, 256>>>(h, ln2w + (size_t)i * D_, ln2b + (size_t)i * D_,
                                  nullptr, Bhi, Blo);
        gemm_w(Bhi, Blo, ff1w + (size_t)i * FF_ * D_, ff1b + (size_t)i * FF_,
               nullptr, nullptr, Fhi, Flo, P_, FF_, D_, FF_, 1, 1, 128, whi, wlo);
        gemm_w(Fhi, Flo, ff2w + (size_t)i * D_ * FF_, ff2b + (size_t)i * D_,
               h, h, nullptr, nullptr, P_, D_, FF_, D_, 0, 0, 64, whi, wlo);
    }

    // 8) final layernorm -> output
    ln_kernel<0><<<P_, 256>>>(h, lnfw, lnfb, out, nullptr, nullptr);
}